// round 1
// baseline (speedup 1.0000x reference)
#include <cuda_runtime.h>
#include <cuda_bf16.h>
#include <math.h>

#define Tn 1024
#define Hn 2048
#define In 1408
#define En 64
#define Fn 8
#define Kn 8
#define Rn 8
#define ISHn 2816
#define TOPKn 6
#define KRn 64

// ---------------- scratch (device globals; allocation-free) ----------------
__device__ float g_soft[Tn * Fn * Kn];
__device__ float g_scalar[Tn * Fn];
__device__ float g_xe[(size_t)Fn * Tn * Hn];
__device__ float g_gug[(size_t)Fn * Tn * In];
__device__ float g_guu[(size_t)Fn * Tn * In];
__device__ float g_mg[(size_t)Fn * Tn * KRn];
__device__ float g_mu[(size_t)Fn * Tn * KRn];
__device__ float g_hmid[(size_t)Fn * Tn * In];
__device__ float g_md[(size_t)Fn * Tn * KRn];
__device__ float g_mixd[(size_t)Fn * Tn * Hn];
__device__ float g_down[(size_t)Fn * Tn * Hn];
__device__ float g_qbtg[(size_t)Fn * In * KRn];
__device__ float g_qbtu[(size_t)Fn * In * KRn];
__device__ float g_qbtd[(size_t)Fn * Hn * KRn];
__device__ float g_shg[(size_t)Tn * ISHn];
__device__ float g_shu[(size_t)Tn * ISHn];
__device__ float g_shm[(size_t)Tn * ISHn];

// ---------------- helpers ----------------
__device__ __forceinline__ float tf32r(float x) {
    float y;
    asm("cvt.rna.tf32.f32 %0, %1;" : "=f"(y) : "f"(x));
    return y;
}

#define MMA_TF32(d, a, b)                                                      \
    asm volatile(                                                              \
        "mma.sync.aligned.m16n8k8.row.col.f32.tf32.tf32.f32 "                  \
        "{%0,%1,%2,%3}, {%4,%5,%6,%7}, {%8,%9}, {%0,%1,%2,%3};\n"              \
        : "+f"((d)[0]), "+f"((d)[1]), "+f"((d)[2]), "+f"((d)[3])               \
        : "r"(__float_as_uint((a)[0])), "r"(__float_as_uint((a)[1])),          \
          "r"(__float_as_uint((a)[2])), "r"(__float_as_uint((a)[3])),          \
          "r"(__float_as_uint((b)[0])), "r"(__float_as_uint((b)[1])))

// ---------------- router (exact fp32: top-k must not flip) ----------------
__global__ void router_kernel(const float* __restrict__ x,
                              const float* __restrict__ gw,
                              const int* __restrict__ inv,
                              float* __restrict__ soft,
                              float* __restrict__ scal) {
    __shared__ float xs[Hn];
    __shared__ float sc[En];
    const int t = blockIdx.x;
    const int tid = threadIdx.x;  // 128 threads
    const float4* xv = reinterpret_cast<const float4*>(x + (size_t)t * Hn);
    for (int i = tid; i < Hn / 4; i += 128)
        reinterpret_cast<float4*>(xs)[i] = xv[i];
    __syncthreads();
    const int lane = tid & 31, w = tid >> 5;
    for (int e = w; e < En; e += 4) {
        const float* g = gw + (size_t)e * Hn;
        float s = 0.f;
        for (int h = lane; h < Hn; h += 32) s += xs[h] * g[h];
#pragma unroll
        for (int o = 16; o; o >>= 1) s += __shfl_xor_sync(0xffffffffu, s, o);
        if (lane == 0) sc[e] = s;
    }
    __syncthreads();
    if (tid == 0) {
        float mx = -1e30f;
        for (int e = 0; e < En; e++) mx = fmaxf(mx, sc[e]);
        float p[En];
        float sum = 0.f;
        for (int e = 0; e < En; e++) { p[e] = expf(sc[e] - mx); sum += p[e]; }
        float is = 1.f / sum;
        for (int e = 0; e < En; e++) p[e] *= is;
        float wv[En];
        for (int e = 0; e < En; e++) wv[e] = 0.f;
        for (int j = 0; j < TOPKn; j++) {
            int best = 0;
            float bv = -1.f;
            for (int e = 0; e < En; e++) {
                if (wv[e] == 0.f && p[e] > bv) { bv = p[e]; best = e; }
            }
            wv[best] = p[best];
        }
        for (int f = 0; f < Fn; f++) {
            float fl[Kn];
            float ssum = 0.f, fmx = -1e30f;
            for (int k = 0; k < Kn; k++) {
                int e = inv[f * Kn + k];
                float v = wv[e];
                ssum += v;
                float l = (v == 0.f) ? -1e9f : v;
                fl[k] = l;
                fmx = fmaxf(fmx, l);
            }
            float es = 0.f, ex[Kn];
            for (int k = 0; k < Kn; k++) { ex[k] = expf(fl[k] - fmx); es += ex[k]; }
            float ies = 1.f / es;
            for (int k = 0; k < Kn; k++)
                soft[((size_t)t * Fn + f) * Kn + k] = ex[k] * ies;
            scal[(size_t)t * Fn + f] = ssum;
        }
    }
}

// ---------------- xe = x + soft @ muW^T ----------------
__global__ void xe_kernel(const float* __restrict__ x,
                          const float* __restrict__ muW,
                          const float* __restrict__ soft,
                          float* __restrict__ xe) {
    size_t idx = (size_t)blockIdx.x * blockDim.x + threadIdx.x;
    if (idx >= (size_t)Fn * Tn * Hn) return;
    int z = (int)(idx / ((size_t)Tn * Hn));
    int rem = (int)(idx % ((size_t)Tn * Hn));
    int t = rem / Hn, h = rem % Hn;
    const float* mw = muW + ((size_t)z * Hn + h) * Kn;
    const float* sf = soft + ((size_t)t * Fn + z) * Kn;
    float s = x[rem];
#pragma unroll
    for (int k = 0; k < Kn; k++) s += sf[k] * mw[k];
    xe[idx] = s;
}

// ---------------- qb transpose: [F,K,Nd,R] -> [F,Nd,K*R] ----------------
__global__ void tq_kernel(const float* __restrict__ qb, float* __restrict__ outp, int Nd) {
    int total = Fn * Nd * KRn;
    int idx = blockIdx.x * blockDim.x + threadIdx.x;
    if (idx >= total) return;
    int z = idx / (Nd * KRn);
    int rem = idx % (Nd * KRn);
    int n = rem >> 6, kr = rem & 63;
    int k = kr >> 3, r = kr & 7;
    outp[idx] = qb[(((size_t)z * Kn + k) * Nd + n) * Rn + r];
}

// ---------------- hmid = silu(gate)*up ----------------
__global__ void fuse_kernel(const float* __restrict__ gg, const float* __restrict__ uu,
                            float* __restrict__ hm) {
    size_t idx = (size_t)blockIdx.x * blockDim.x + threadIdx.x;
    if (idx >= (size_t)Fn * Tn * In) return;
    float g = gg[idx], u = uu[idx];
    hm[idx] = g / (1.f + expf(-g)) * u;
}

__global__ void swiglu_kernel(const float* __restrict__ gg, const float* __restrict__ uu,
                              float* __restrict__ hm) {
    size_t idx = (size_t)blockIdx.x * blockDim.x + threadIdx.x;
    if (idx >= (size_t)Tn * ISHn) return;
    float g = gg[idx], u = uu[idx];
    hm[idx] = g / (1.f + expf(-g)) * u;
}

// ---------------- out += sum_z down[z] (deterministic) ----------------
__global__ void reduce_kernel(float* __restrict__ out, const float* __restrict__ down) {
    int idx = blockIdx.x * blockDim.x + threadIdx.x;
    if (idx >= Tn * Hn) return;
    float s = out[idx];
#pragma unroll
    for (int z = 0; z < Fn; z++) s += down[(size_t)z * Tn * Hn + idx];
    out[idx] = s;
}

// ---------------- generic tf32 GEMM: C[MxN] = A[MxK] * B[NxK]^T ----------------
// MODE 0: C=acc
// MODE 1: C=acc*soft[t, z, n>>3]
// MODE 2: C=C + colscale[n]*acc   (in-place add)
// MODE 3: C=colscale[n]*acc
// MODE 4: C=rowscal[t*Fn+z]*(acc + mixadd[t,n])
#define SM_LD 36
#define SM_BUF (128 * SM_LD)
#define SMEM_BYTES (4 * SM_BUF * 4)

template <int MODE>
__global__ void __launch_bounds__(256)
gemm_tn(const float* __restrict__ A, int lda, size_t sA,
        const float* __restrict__ B, int ldb, size_t sB,
        float* __restrict__ C, int ldc, size_t sC,
        int N, int Ktot,
        const float* __restrict__ soft,
        const float* __restrict__ rowscal,
        const float* __restrict__ colscale, size_t sCs,
        const float* __restrict__ mixadd) {
    const int z = blockIdx.z;
    A += (size_t)z * sA;
    B += (size_t)z * sB;
    C += (size_t)z * sC;
    const float* cs = (MODE == 2 || MODE == 3) ? colscale + (size_t)z * sCs : nullptr;
    const float* mixp = (MODE == 4) ? mixadd + (size_t)z * sC : nullptr;

    extern __shared__ float smf[];
    float* As = smf;
    float* Bs = smf + 2 * SM_BUF;
    const int bm = blockIdx.y * 128, bn = blockIdx.x * 128;
    const int tid = threadIdx.x, lane = tid & 31, wid = tid >> 5;
    const int wm = (wid >> 2) * 64, wn = (wid & 3) * 32;

    int arow[4], kq4[4];
#pragma unroll
    for (int i = 0; i < 4; i++) {
        int lin = tid + i * 256;
        arow[i] = lin >> 3;
        kq4[i] = (lin & 7) << 2;
    }
    float4 ra[4], rb[4];
    float acc[4][4][4];
#pragma unroll
    for (int a = 0; a < 4; a++)
#pragma unroll
        for (int b = 0; b < 4; b++)
#pragma unroll
            for (int c = 0; c < 4; c++) acc[a][b][c] = 0.f;

    auto ldg = [&](int k0) {
#pragma unroll
        for (int i = 0; i < 4; i++) {
            ra[i] = *reinterpret_cast<const float4*>(A + (size_t)(bm + arow[i]) * lda + k0 + kq4[i]);
            int n = bn + arow[i];
            rb[i] = (n < N)
                        ? *reinterpret_cast<const float4*>(B + (size_t)n * ldb + k0 + kq4[i])
                        : make_float4(0.f, 0.f, 0.f, 0.f);
        }
    };
    auto sts = [&](int buf) {
#pragma unroll
        for (int i = 0; i < 4; i++) {
            float4 a = ra[i];
            a.x = tf32r(a.x); a.y = tf32r(a.y); a.z = tf32r(a.z); a.w = tf32r(a.w);
            *reinterpret_cast<float4*>(&As[buf * SM_BUF + arow[i] * SM_LD + kq4[i]]) = a;
            float4 b = rb[i];
            b.x = tf32r(b.x); b.y = tf32r(b.y); b.z = tf32r(b.z); b.w = tf32r(b.w);
            *reinterpret_cast<float4*>(&Bs[buf * SM_BUF + arow[i] * SM_LD + kq4[i]]) = b;
        }
    };

    ldg(0);
    sts(0);
    __syncthreads();
    const int KT = Ktot >> 5;
    for (int kt = 0; kt < KT; kt++) {
        int cur = kt & 1;
        if (kt + 1 < KT) ldg((kt + 1) << 5);
        const float* Ab = As + cur * SM_BUF;
        const float* Bb = Bs + cur * SM_BUF;
#pragma unroll
        for (int ks = 0; ks < 4; ks++) {
            int kk = ks * 8 + (lane & 3);
            float a[4][4], b[4][2];
#pragma unroll
            for (int mi = 0; mi < 4; mi++) {
                const float* p = Ab + (wm + mi * 16 + (lane >> 2)) * SM_LD + kk;
                a[mi][0] = p[0];
                a[mi][1] = p[8 * SM_LD];
                a[mi][2] = p[4];
                a[mi][3] = p[8 * SM_LD + 4];
            }
#pragma unroll
            for (int ni = 0; ni < 4; ni++) {
                const float* q = Bb + (wn + ni * 8 + (lane >> 2)) * SM_LD + kk;
                b[ni][0] = q[0];
                b[ni][1] = q[4];
            }
#pragma unroll
            for (int mi = 0; mi < 4; mi++)
#pragma unroll
                for (int ni = 0; ni < 4; ni++) MMA_TF32(acc[mi][ni], a[mi], b[ni]);
        }
        if (kt + 1 < KT) {
            sts(cur ^ 1);
            __syncthreads();
        }
    }

    // epilogue
#pragma unroll
    for (int mi = 0; mi < 4; mi++) {
#pragma unroll
        for (int ni = 0; ni < 4; ni++) {
            int cb = bn + wn + ni * 8;
            if (cb >= N) continue;
            int c = cb + ((lane & 3) << 1);
#pragma unroll
            for (int hh = 0; hh < 2; hh++) {
                int r = bm + wm + mi * 16 + (lane >> 2) + hh * 8;
                float v0 = acc[mi][ni][hh * 2 + 0];
                float v1 = acc[mi][ni][hh * 2 + 1];
                size_t off = (size_t)r * ldc + c;
                if (MODE == 1) {
                    float s = soft[((size_t)r * Fn + z) * Kn + (c >> 3)];
                    v0 *= s;
                    v1 *= s;
                } else if (MODE == 2) {
                    float2 prev = *reinterpret_cast<const float2*>(&C[off]);
                    v0 = prev.x + cs[c] * v0;
                    v1 = prev.y + cs[c + 1] * v1;
                } else if (MODE == 3) {
                    v0 *= cs[c];
                    v1 *= cs[c + 1];
                } else if (MODE == 4) {
                    float rs = rowscal[(size_t)r * Fn + z];
                    float2 mv = *reinterpret_cast<const float2*>(&mixp[off]);
                    v0 = rs * (v0 + mv.x);
                    v1 = rs * (v1 + mv.y);
                }
                *reinterpret_cast<float2*>(&C[off]) = make_float2(v0, v1);
            }
        }
    }
}

// ---------------- host ----------------
#define SYMP(v) ({ void* _p = nullptr; cudaGetSymbolAddress(&_p, v); (float*)_p; })

extern "C" void kernel_launch(void* const* d_in, const int* in_sizes, int n_in,
                              void* d_out, int out_size) {
    const float* x          = (const float*)d_in[0];
    const float* gate_wt    = (const float*)d_in[1];
    const int*   inv        = (const int*)d_in[2];
    const float* mask_up_W  = (const float*)d_in[3];
    const float* gate_W     = (const float*)d_in[4];
    const float* gate_qa    = (const float*)d_in[5];
    const float* gate_qb    = (const float*)d_in[6];
    const float* gate_scale = (const float*)d_in[7];
    const float* up_W       = (const float*)d_in[8];
    const float* up_qa      = (const float*)d_in[9];
    const float* up_qb      = (const float*)d_in[10];
    const float* up_scale   = (const float*)d_in[11];
    const float* down_W     = (const float*)d_in[12];
    const float* down_qa    = (const float*)d_in[13];
    const float* down_qb    = (const float*)d_in[14];
    const float* down_scale = (const float*)d_in[15];
    const float* sh_gate_W  = (const float*)d_in[16];
    const float* sh_up_W    = (const float*)d_in[17];
    const float* sh_down_W  = (const float*)d_in[18];
    float* out = (float*)d_out;

    float* p_soft = SYMP(g_soft);
    float* p_scal = SYMP(g_scalar);
    float* p_xe   = SYMP(g_xe);
    float* p_gug  = SYMP(g_gug);
    float* p_guu  = SYMP(g_guu);
    float* p_mg   = SYMP(g_mg);
    float* p_mu   = SYMP(g_mu);
    float* p_hmid = SYMP(g_hmid);
    float* p_md   = SYMP(g_md);
    float* p_mixd = SYMP(g_mixd);
    float* p_down = SYMP(g_down);
    float* p_qbtg = SYMP(g_qbtg);
    float* p_qbtu = SYMP(g_qbtu);
    float* p_qbtd = SYMP(g_qbtd);
    float* p_shg  = SYMP(g_shg);
    float* p_shu  = SYMP(g_shu);
    float* p_shm  = SYMP(g_shm);

    cudaFuncSetAttribute(gemm_tn<0>, cudaFuncAttributeMaxDynamicSharedMemorySize, SMEM_BYTES);
    cudaFuncSetAttribute(gemm_tn<1>, cudaFuncAttributeMaxDynamicSharedMemorySize, SMEM_BYTES);
    cudaFuncSetAttribute(gemm_tn<2>, cudaFuncAttributeMaxDynamicSharedMemorySize, SMEM_BYTES);
    cudaFuncSetAttribute(gemm_tn<3>, cudaFuncAttributeMaxDynamicSharedMemorySize, SMEM_BYTES);
    cudaFuncSetAttribute(gemm_tn<4>, cudaFuncAttributeMaxDynamicSharedMemorySize, SMEM_BYTES);

#define GRID(N, zc) dim3(((N) + 127) / 128, Tn / 128, zc)

    // 1. router (exact fp32)
    router_kernel<<<Tn, 128>>>(x, gate_wt, inv, p_soft, p_scal);

    // 2. xe[z,t,h] = x + soft @ muW^T
    {
        size_t cnt = (size_t)Fn * Tn * Hn;
        xe_kernel<<<(int)((cnt + 255) / 256), 256>>>(x, mask_up_W, p_soft, p_xe);
    }

    // 3. qb transposes
    tq_kernel<<<(Fn * In * KRn + 255) / 256, 256>>>(gate_qb, p_qbtg, In);
    tq_kernel<<<(Fn * In * KRn + 255) / 256, 256>>>(up_qb, p_qbtu, In);
    tq_kernel<<<(Fn * Hn * KRn + 255) / 256, 256>>>(down_qb, p_qbtd, Hn);

    // 4. gate/up main GEMMs
    gemm_tn<0><<<GRID(In, Fn), 256, SMEM_BYTES>>>(
        p_xe, Hn, (size_t)Tn * Hn, gate_W, Hn, (size_t)In * Hn,
        p_gug, In, (size_t)Tn * In, In, Hn, nullptr, nullptr, nullptr, 0, nullptr);
    gemm_tn<0><<<GRID(In, Fn), 256, SMEM_BYTES>>>(
        p_xe, Hn, (size_t)Tn * Hn, up_W, Hn, (size_t)In * Hn,
        p_guu, In, (size_t)Tn * In, In, Hn, nullptr, nullptr, nullptr, 0, nullptr);

    // 5. LoRA "a" GEMMs with soft-weight epilogue: m = (xe @ qa^T) * soft
    gemm_tn<1><<<GRID(KRn, Fn), 256, SMEM_BYTES>>>(
        p_xe, Hn, (size_t)Tn * Hn, gate_qa, Hn, (size_t)KRn * Hn,
        p_mg, KRn, (size_t)Tn * KRn, KRn, Hn, p_soft, nullptr, nullptr, 0, nullptr);
    gemm_tn<1><<<GRID(KRn, Fn), 256, SMEM_BYTES>>>(
        p_xe, Hn, (size_t)Tn * Hn, up_qa, Hn, (size_t)KRn * Hn,
        p_mu, KRn, (size_t)Tn * KRn, KRn, Hn, p_soft, nullptr, nullptr, 0, nullptr);

    // 6. mix GEMMs, fused in-place: gu += scale[n] * (m @ qbt^T)
    gemm_tn<2><<<GRID(In, Fn), 256, SMEM_BYTES>>>(
        p_mg, KRn, (size_t)Tn * KRn, p_qbtg, KRn, (size_t)In * KRn,
        p_gug, In, (size_t)Tn * In, In, KRn, nullptr, nullptr, gate_scale, In, nullptr);
    gemm_tn<2><<<GRID(In, Fn), 256, SMEM_BYTES>>>(
        p_mu, KRn, (size_t)Tn * KRn, p_qbtu, KRn, (size_t)In * KRn,
        p_guu, In, (size_t)Tn * In, In, KRn, nullptr, nullptr, up_scale, In, nullptr);

    // 7. hmid = silu(gate)*up
    {
        size_t cnt = (size_t)Fn * Tn * In;
        fuse_kernel<<<(int)((cnt + 255) / 256), 256>>>(p_gug, p_guu, p_hmid);
    }

    // 8. down LoRA a: md = (hmid @ dqa^T) * soft
    gemm_tn<1><<<GRID(KRn, Fn), 256, SMEM_BYTES>>>(
        p_hmid, In, (size_t)Tn * In, down_qa, In, (size_t)KRn * In,
        p_md, KRn, (size_t)Tn * KRn, KRn, In, p_soft, nullptr, nullptr, 0, nullptr);

    // 9. mixd = down_scale[n] * (md @ qbtd^T)
    gemm_tn<3><<<GRID(Hn, Fn), 256, SMEM_BYTES>>>(
        p_md, KRn, (size_t)Tn * KRn, p_qbtd, KRn, (size_t)Hn * KRn,
        p_mixd, Hn, (size_t)Tn * Hn, Hn, KRn, nullptr, nullptr, down_scale, Hn, nullptr);

    // 10. down GEMM fused: down = scalar[t,z]*(hmid @ dW^T + mixd)
    gemm_tn<4><<<GRID(Hn, Fn), 256, SMEM_BYTES>>>(
        p_hmid, In, (size_t)Tn * In, down_W, In, (size_t)Hn * In,
        p_down, Hn, (size_t)Tn * Hn, Hn, In, nullptr, p_scal, nullptr, 0, p_mixd);

    // 11. shared path
    gemm_tn<0><<<GRID(ISHn, 1), 256, SMEM_BYTES>>>(
        x, Hn, 0, sh_gate_W, Hn, 0,
        p_shg, ISHn, 0, ISHn, Hn, nullptr, nullptr, nullptr, 0, nullptr);
    gemm_tn<0><<<GRID(ISHn, 1), 256, SMEM_BYTES>>>(
        x, Hn, 0, sh_up_W, Hn, 0,
        p_shu, ISHn, 0, ISHn, Hn, nullptr, nullptr, nullptr, 0, nullptr);
    {
        size_t cnt = (size_t)Tn * ISHn;
        swiglu_kernel<<<(int)((cnt + 255) / 256), 256>>>(p_shg, p_shu, p_shm);
    }
    gemm_tn<0><<<GRID(Hn, 1), 256, SMEM_BYTES>>>(
        p_shm, ISHn, 0, sh_down_W, ISHn, 0,
        out, Hn, 0, Hn, ISHn, nullptr, nullptr, nullptr, 0, nullptr);

    // 12. out += sum_z down[z]
    reduce_kernel<<<(Tn * Hn + 255) / 256, 256>>>(out, p_down);

#undef GRID
    (void)in_sizes; (void)n_in; (void)out_size;
}

// round 2
// speedup vs baseline: 1.1703x; 1.1703x over previous
#include <cuda_runtime.h>
#include <cuda_bf16.h>
#include <math.h>

#define Tn 1024
#define Hn 2048
#define In 1408
#define En 64
#define Fn 8
#define Kn 8
#define Rn 8
#define ISHn 2816
#define TOPKn 6
#define KRn 64

// ---------------- scratch (device globals; allocation-free) ----------------
__device__ float g_soft[Tn * Fn * Kn];
__device__ float g_scalar[Tn * Fn];
__device__ int   g_cnt[Fn];
__device__ int   g_tok[Fn * Tn];
__device__ int   g_pos[Fn * Tn];
__device__ float g_xe[(size_t)Fn * Tn * Hn];
__device__ float g_gug[(size_t)Fn * Tn * In];
__device__ float g_guu[(size_t)Fn * Tn * In];
__device__ float g_mg[(size_t)Fn * Tn * KRn];
__device__ float g_mu[(size_t)Fn * Tn * KRn];
__device__ float g_hmid[(size_t)Fn * Tn * In];
__device__ float g_md[(size_t)Fn * Tn * KRn];
__device__ float g_mixd[(size_t)Fn * Tn * Hn];
__device__ float g_down[(size_t)Fn * Tn * Hn];
__device__ float g_qbtg[(size_t)Fn * In * KRn];
__device__ float g_qbtu[(size_t)Fn * In * KRn];
__device__ float g_qbtd[(size_t)Fn * Hn * KRn];
__device__ float g_shg[(size_t)Tn * ISHn];
__device__ float g_shu[(size_t)Tn * ISHn];
__device__ float g_shm[(size_t)Tn * ISHn];

// ---------------- helpers ----------------
__device__ __forceinline__ float tf32r(float x) {
    float y;
    asm("cvt.rna.tf32.f32 %0, %1;" : "=f"(y) : "f"(x));
    return y;
}

#define MMA_TF32(d, a, b)                                                      \
    asm volatile(                                                              \
        "mma.sync.aligned.m16n8k8.row.col.f32.tf32.tf32.f32 "                  \
        "{%0,%1,%2,%3}, {%4,%5,%6,%7}, {%8,%9}, {%0,%1,%2,%3};\n"              \
        : "+f"((d)[0]), "+f"((d)[1]), "+f"((d)[2]), "+f"((d)[3])               \
        : "r"(__float_as_uint((a)[0])), "r"(__float_as_uint((a)[1])),          \
          "r"(__float_as_uint((a)[2])), "r"(__float_as_uint((a)[3])),          \
          "r"(__float_as_uint((b)[0])), "r"(__float_as_uint((b)[1])))

// ---------------- router (exact fp32: top-k must not flip) ----------------
__global__ void router_kernel(const float* __restrict__ x,
                              const float* __restrict__ gw,
                              const int* __restrict__ inv,
                              float* __restrict__ soft,
                              float* __restrict__ scal) {
    __shared__ float xs[Hn];
    __shared__ float sc[En];
    const int t = blockIdx.x;
    const int tid = threadIdx.x;  // 128 threads
    const float4* xv = reinterpret_cast<const float4*>(x + (size_t)t * Hn);
    for (int i = tid; i < Hn / 4; i += 128)
        reinterpret_cast<float4*>(xs)[i] = xv[i];
    __syncthreads();
    const int lane = tid & 31, w = tid >> 5;
    for (int e = w; e < En; e += 4) {
        const float* g = gw + (size_t)e * Hn;
        float s = 0.f;
        for (int h = lane; h < Hn; h += 32) s += xs[h] * g[h];
#pragma unroll
        for (int o = 16; o; o >>= 1) s += __shfl_xor_sync(0xffffffffu, s, o);
        if (lane == 0) sc[e] = s;
    }
    __syncthreads();
    if (tid == 0) {
        float mx = -1e30f;
        for (int e = 0; e < En; e++) mx = fmaxf(mx, sc[e]);
        float p[En];
        float sum = 0.f;
        for (int e = 0; e < En; e++) { p[e] = expf(sc[e] - mx); sum += p[e]; }
        float is = 1.f / sum;
        for (int e = 0; e < En; e++) p[e] *= is;
        float wv[En];
        for (int e = 0; e < En; e++) wv[e] = 0.f;
        for (int j = 0; j < TOPKn; j++) {
            int best = 0;
            float bv = -1.f;
            for (int e = 0; e < En; e++) {
                if (wv[e] == 0.f && p[e] > bv) { bv = p[e]; best = e; }
            }
            wv[best] = p[best];
        }
        for (int f = 0; f < Fn; f++) {
            float fl[Kn];
            float ssum = 0.f, fmx = -1e30f;
            for (int k = 0; k < Kn; k++) {
                int e = inv[f * Kn + k];
                float v = wv[e];
                ssum += v;
                float l = (v == 0.f) ? -1e9f : v;
                fl[k] = l;
                fmx = fmaxf(fmx, l);
            }
            float es = 0.f, ex[Kn];
            for (int k = 0; k < Kn; k++) { ex[k] = expf(fl[k] - fmx); es += ex[k]; }
            float ies = 1.f / es;
            for (int k = 0; k < Kn; k++)
                soft[((size_t)t * Fn + f) * Kn + k] = ex[k] * ies;
            scal[(size_t)t * Fn + f] = ssum;
        }
    }
}

// ---------------- deterministic per-group token compaction ----------------
__global__ void compact_kernel(const float* __restrict__ scal,
                               int* __restrict__ cnt,
                               int* __restrict__ tok,
                               int* __restrict__ pos) {
    const int z = blockIdx.x;
    const int t = threadIdx.x;  // Tn threads
    __shared__ int sbuf[Tn];
    int active = (scal[(size_t)t * Fn + z] != 0.f) ? 1 : 0;
    sbuf[t] = active;
    __syncthreads();
    // Hillis–Steele inclusive scan (deterministic)
    for (int off = 1; off < Tn; off <<= 1) {
        int v = (t >= off) ? sbuf[t - off] : 0;
        __syncthreads();
        sbuf[t] += v;
        __syncthreads();
    }
    int incl = sbuf[t];
    if (active) {
        tok[z * Tn + incl - 1] = t;
        pos[z * Tn + t] = incl - 1;
    } else {
        pos[z * Tn + t] = -1;
    }
    if (t == Tn - 1) cnt[z] = incl;
}

// ---------------- xe (compacted): xe[z,i,h] = x[tok] + soft @ muW^T --------
__global__ void xe_kernel(const float* __restrict__ x,
                          const float* __restrict__ muW,
                          const float* __restrict__ soft,
                          const int* __restrict__ cnt,
                          const int* __restrict__ tok,
                          float* __restrict__ xe) {
    size_t idx = (size_t)blockIdx.x * blockDim.x + threadIdx.x;
    if (idx >= (size_t)Fn * Tn * Hn) return;
    int z = (int)(idx / ((size_t)Tn * Hn));
    int rem = (int)(idx % ((size_t)Tn * Hn));
    int i = rem / Hn, h = rem % Hn;
    if (i >= cnt[z]) return;
    int t = tok[z * Tn + i];
    const float* mw = muW + ((size_t)z * Hn + h) * Kn;
    const float* sf = soft + ((size_t)t * Fn + z) * Kn;
    float s = x[(size_t)t * Hn + h];
#pragma unroll
    for (int k = 0; k < Kn; k++) s += sf[k] * mw[k];
    xe[idx] = s;
}

// ---------------- qb transpose: [F,K,Nd,R] -> [F,Nd,K*R] ----------------
__global__ void tq_kernel(const float* __restrict__ qb, float* __restrict__ outp, int Nd) {
    int total = Fn * Nd * KRn;
    int idx = blockIdx.x * blockDim.x + threadIdx.x;
    if (idx >= total) return;
    int z = idx / (Nd * KRn);
    int rem = idx % (Nd * KRn);
    int n = rem >> 6, kr = rem & 63;
    int k = kr >> 3, r = kr & 7;
    outp[idx] = qb[(((size_t)z * Kn + k) * Nd + n) * Rn + r];
}

// ---------------- hmid = silu(gate)*up (compacted rows only) --------------
__global__ void fuse_kernel(const float* __restrict__ gg, const float* __restrict__ uu,
                            const int* __restrict__ cnt,
                            float* __restrict__ hm) {
    size_t idx = (size_t)blockIdx.x * blockDim.x + threadIdx.x;
    if (idx >= (size_t)Fn * Tn * In) return;
    int z = (int)(idx / ((size_t)Tn * In));
    int i = (int)((idx % ((size_t)Tn * In)) / In);
    if (i >= cnt[z]) return;
    float g = gg[idx], u = uu[idx];
    hm[idx] = g / (1.f + expf(-g)) * u;
}

__global__ void swiglu_kernel(const float* __restrict__ gg, const float* __restrict__ uu,
                              float* __restrict__ hm) {
    size_t idx = (size_t)blockIdx.x * blockDim.x + threadIdx.x;
    if (idx >= (size_t)Tn * ISHn) return;
    float g = gg[idx], u = uu[idx];
    hm[idx] = g / (1.f + expf(-g)) * u;
}

// ---------------- out[t] += sum_z active: down[z][pos[z,t]] ----------------
__global__ void reduce_kernel(float* __restrict__ out, const float* __restrict__ down,
                              const int* __restrict__ pos) {
    int idx = blockIdx.x * blockDim.x + threadIdx.x;
    if (idx >= Tn * Hn) return;
    int t = idx / Hn, h = idx % Hn;
    float s = out[idx];
#pragma unroll
    for (int z = 0; z < Fn; z++) {
        int p = pos[z * Tn + t];
        if (p >= 0) s += down[((size_t)z * Tn + p) * Hn + h];
    }
    out[idx] = s;
}

// ---------------- generic tf32 GEMM: C[MxN] = A[MxK] * B[NxK]^T ----------------
// M is bounded per-z by cnt[z] when cntp != nullptr (compacted rows).
// MODE 0: C=acc
// MODE 1: C=acc*soft[tok[r], z, n>>3]
// MODE 2: C=C + colscale[n]*acc   (in-place add)
// MODE 3: C=colscale[n]*acc
// MODE 4: C=rowscal[tok[r]*Fn+z]*(acc + mixadd[z,r,n])
#define SM_LD 36
#define SM_BUF (128 * SM_LD)
#define SMEM_BYTES (4 * SM_BUF * 4)

template <int MODE>
__global__ void __launch_bounds__(256)
gemm_tn(const float* __restrict__ A, int lda, size_t sA,
        const float* __restrict__ B, int ldb, size_t sB,
        float* __restrict__ C, int ldc, size_t sC,
        int N, int Ktot,
        const float* __restrict__ soft,
        const float* __restrict__ rowscal,
        const float* __restrict__ colscale, size_t sCs,
        const float* __restrict__ mixadd,
        const int* __restrict__ cntp,
        const int* __restrict__ tokp) {
    const int z = blockIdx.z;
    const int Mz = cntp ? cntp[z] : Tn;
    const int bm = blockIdx.y * 128, bn = blockIdx.x * 128;
    if (bm >= Mz) return;
    A += (size_t)z * sA;
    B += (size_t)z * sB;
    C += (size_t)z * sC;
    const float* cs = (MODE == 2 || MODE == 3) ? colscale + (size_t)z * sCs : nullptr;
    const float* mixp = (MODE == 4) ? mixadd + (size_t)z * sC : nullptr;
    const int* tk = (MODE == 1 || MODE == 4) ? tokp + z * Tn : nullptr;

    extern __shared__ float smf[];
    float* As = smf;
    float* Bs = smf + 2 * SM_BUF;
    const int tid = threadIdx.x, lane = tid & 31, wid = tid >> 5;
    const int wm = (wid >> 2) * 64, wn = (wid & 3) * 32;

    int arow[4], kq4[4];
#pragma unroll
    for (int i = 0; i < 4; i++) {
        int lin = tid + i * 256;
        arow[i] = lin >> 3;
        kq4[i] = (lin & 7) << 2;
    }
    float4 ra[4], rb[4];
    float acc[4][4][4];
#pragma unroll
    for (int a = 0; a < 4; a++)
#pragma unroll
        for (int b = 0; b < 4; b++)
#pragma unroll
            for (int c = 0; c < 4; c++) acc[a][b][c] = 0.f;

    auto ldg = [&](int k0) {
#pragma unroll
        for (int i = 0; i < 4; i++) {
            int m = bm + arow[i];
            ra[i] = (m < Mz)
                        ? *reinterpret_cast<const float4*>(A + (size_t)m * lda + k0 + kq4[i])
                        : make_float4(0.f, 0.f, 0.f, 0.f);
            int n = bn + arow[i];
            rb[i] = (n < N)
                        ? *reinterpret_cast<const float4*>(B + (size_t)n * ldb + k0 + kq4[i])
                        : make_float4(0.f, 0.f, 0.f, 0.f);
        }
    };
    auto sts = [&](int buf) {
#pragma unroll
        for (int i = 0; i < 4; i++) {
            float4 a = ra[i];
            a.x = tf32r(a.x); a.y = tf32r(a.y); a.z = tf32r(a.z); a.w = tf32r(a.w);
            *reinterpret_cast<float4*>(&As[buf * SM_BUF + arow[i] * SM_LD + kq4[i]]) = a;
            float4 b = rb[i];
            b.x = tf32r(b.x); b.y = tf32r(b.y); b.z = tf32r(b.z); b.w = tf32r(b.w);
            *reinterpret_cast<float4*>(&Bs[buf * SM_BUF + arow[i] * SM_LD + kq4[i]]) = b;
        }
    };

    ldg(0);
    sts(0);
    __syncthreads();
    const int KT = Ktot >> 5;
    for (int kt = 0; kt < KT; kt++) {
        int cur = kt & 1;
        if (kt + 1 < KT) ldg((kt + 1) << 5);
        const float* Ab = As + cur * SM_BUF;
        const float* Bb = Bs + cur * SM_BUF;
#pragma unroll
        for (int ks = 0; ks < 4; ks++) {
            int kk = ks * 8 + (lane & 3);
            float a[4][4], b[4][2];
#pragma unroll
            for (int mi = 0; mi < 4; mi++) {
                const float* p = Ab + (wm + mi * 16 + (lane >> 2)) * SM_LD + kk;
                a[mi][0] = p[0];
                a[mi][1] = p[8 * SM_LD];
                a[mi][2] = p[4];
                a[mi][3] = p[8 * SM_LD + 4];
            }
#pragma unroll
            for (int ni = 0; ni < 4; ni++) {
                const float* q = Bb + (wn + ni * 8 + (lane >> 2)) * SM_LD + kk;
                b[ni][0] = q[0];
                b[ni][1] = q[4];
            }
#pragma unroll
            for (int mi = 0; mi < 4; mi++)
#pragma unroll
                for (int ni = 0; ni < 4; ni++) MMA_TF32(acc[mi][ni], a[mi], b[ni]);
        }
        if (kt + 1 < KT) {
            sts(cur ^ 1);
            __syncthreads();
        }
    }

    // epilogue
#pragma unroll
    for (int mi = 0; mi < 4; mi++) {
#pragma unroll
        for (int ni = 0; ni < 4; ni++) {
            int cb = bn + wn + ni * 8;
            if (cb >= N) continue;
            int c = cb + ((lane & 3) << 1);
#pragma unroll
            for (int hh = 0; hh < 2; hh++) {
                int r = bm + wm + mi * 16 + (lane >> 2) + hh * 8;
                if (r >= Mz) continue;
                float v0 = acc[mi][ni][hh * 2 + 0];
                float v1 = acc[mi][ni][hh * 2 + 1];
                size_t off = (size_t)r * ldc + c;
                if (MODE == 1) {
                    float s = soft[((size_t)tk[r] * Fn + z) * Kn + (c >> 3)];
                    v0 *= s;
                    v1 *= s;
                } else if (MODE == 2) {
                    float2 prev = *reinterpret_cast<const float2*>(&C[off]);
                    v0 = prev.x + cs[c] * v0;
                    v1 = prev.y + cs[c + 1] * v1;
                } else if (MODE == 3) {
                    v0 *= cs[c];
                    v1 *= cs[c + 1];
                } else if (MODE == 4) {
                    float rs = rowscal[(size_t)tk[r] * Fn + z];
                    float2 mv = *reinterpret_cast<const float2*>(&mixp[off]);
                    v0 = rs * (v0 + mv.x);
                    v1 = rs * (v1 + mv.y);
                }
                *reinterpret_cast<float2*>(&C[off]) = make_float2(v0, v1);
            }
        }
    }
}

// ---------------- host ----------------
#define SYMP(v, T) ({ void* _p = nullptr; cudaGetSymbolAddress(&_p, v); (T*)_p; })

extern "C" void kernel_launch(void* const* d_in, const int* in_sizes, int n_in,
                              void* d_out, int out_size) {
    const float* x          = (const float*)d_in[0];
    const float* gate_wt    = (const float*)d_in[1];
    const int*   inv        = (const int*)d_in[2];
    const float* mask_up_W  = (const float*)d_in[3];
    const float* gate_W     = (const float*)d_in[4];
    const float* gate_qa    = (const float*)d_in[5];
    const float* gate_qb    = (const float*)d_in[6];
    const float* gate_scale = (const float*)d_in[7];
    const float* up_W       = (const float*)d_in[8];
    const float* up_qa      = (const float*)d_in[9];
    const float* up_qb      = (const float*)d_in[10];
    const float* up_scale   = (const float*)d_in[11];
    const float* down_W     = (const float*)d_in[12];
    const float* down_qa    = (const float*)d_in[13];
    const float* down_qb    = (const float*)d_in[14];
    const float* down_scale = (const float*)d_in[15];
    const float* sh_gate_W  = (const float*)d_in[16];
    const float* sh_up_W    = (const float*)d_in[17];
    const float* sh_down_W  = (const float*)d_in[18];
    float* out = (float*)d_out;

    float* p_soft = SYMP(g_soft, float);
    float* p_scal = SYMP(g_scalar, float);
    int*   p_cnt  = SYMP(g_cnt, int);
    int*   p_tok  = SYMP(g_tok, int);
    int*   p_pos  = SYMP(g_pos, int);
    float* p_xe   = SYMP(g_xe, float);
    float* p_gug  = SYMP(g_gug, float);
    float* p_guu  = SYMP(g_guu, float);
    float* p_mg   = SYMP(g_mg, float);
    float* p_mu   = SYMP(g_mu, float);
    float* p_hmid = SYMP(g_hmid, float);
    float* p_md   = SYMP(g_md, float);
    float* p_mixd = SYMP(g_mixd, float);
    float* p_down = SYMP(g_down, float);
    float* p_qbtg = SYMP(g_qbtg, float);
    float* p_qbtu = SYMP(g_qbtu, float);
    float* p_qbtd = SYMP(g_qbtd, float);
    float* p_shg  = SYMP(g_shg, float);
    float* p_shu  = SYMP(g_shu, float);
    float* p_shm  = SYMP(g_shm, float);

    cudaFuncSetAttribute(gemm_tn<0>, cudaFuncAttributeMaxDynamicSharedMemorySize, SMEM_BYTES);
    cudaFuncSetAttribute(gemm_tn<1>, cudaFuncAttributeMaxDynamicSharedMemorySize, SMEM_BYTES);
    cudaFuncSetAttribute(gemm_tn<2>, cudaFuncAttributeMaxDynamicSharedMemorySize, SMEM_BYTES);
    cudaFuncSetAttribute(gemm_tn<3>, cudaFuncAttributeMaxDynamicSharedMemorySize, SMEM_BYTES);
    cudaFuncSetAttribute(gemm_tn<4>, cudaFuncAttributeMaxDynamicSharedMemorySize, SMEM_BYTES);

#define GRID(N, zc) dim3(((N) + 127) / 128, Tn / 128, zc)

    // 1. router (exact fp32)
    router_kernel<<<Tn, 128>>>(x, gate_wt, inv, p_soft, p_scal);

    // 1b. deterministic token compaction per group
    compact_kernel<<<Fn, Tn>>>(p_scal, p_cnt, p_tok, p_pos);

    // 2. xe[z,i,h] = x[tok] + soft @ muW^T (compacted)
    {
        size_t cntT = (size_t)Fn * Tn * Hn;
        xe_kernel<<<(int)((cntT + 255) / 256), 256>>>(x, mask_up_W, p_soft, p_cnt, p_tok, p_xe);
    }

    // 3. qb transposes
    tq_kernel<<<(Fn * In * KRn + 255) / 256, 256>>>(gate_qb, p_qbtg, In);
    tq_kernel<<<(Fn * In * KRn + 255) / 256, 256>>>(up_qb, p_qbtu, In);
    tq_kernel<<<(Fn * Hn * KRn + 255) / 256, 256>>>(down_qb, p_qbtd, Hn);

    // 4. gate/up main GEMMs (compacted M)
    gemm_tn<0><<<GRID(In, Fn), 256, SMEM_BYTES>>>(
        p_xe, Hn, (size_t)Tn * Hn, gate_W, Hn, (size_t)In * Hn,
        p_gug, In, (size_t)Tn * In, In, Hn, nullptr, nullptr, nullptr, 0, nullptr, p_cnt, nullptr);
    gemm_tn<0><<<GRID(In, Fn), 256, SMEM_BYTES>>>(
        p_xe, Hn, (size_t)Tn * Hn, up_W, Hn, (size_t)In * Hn,
        p_guu, In, (size_t)Tn * In, In, Hn, nullptr, nullptr, nullptr, 0, nullptr, p_cnt, nullptr);

    // 5. LoRA "a" GEMMs with soft-weight epilogue
    gemm_tn<1><<<GRID(KRn, Fn), 256, SMEM_BYTES>>>(
        p_xe, Hn, (size_t)Tn * Hn, gate_qa, Hn, (size_t)KRn * Hn,
        p_mg, KRn, (size_t)Tn * KRn, KRn, Hn, p_soft, nullptr, nullptr, 0, nullptr, p_cnt, p_tok);
    gemm_tn<1><<<GRID(KRn, Fn), 256, SMEM_BYTES>>>(
        p_xe, Hn, (size_t)Tn * Hn, up_qa, Hn, (size_t)KRn * Hn,
        p_mu, KRn, (size_t)Tn * KRn, KRn, Hn, p_soft, nullptr, nullptr, 0, nullptr, p_cnt, p_tok);

    // 6. mix GEMMs, fused in-place: gu += scale[n] * (m @ qbt^T)
    gemm_tn<2><<<GRID(In, Fn), 256, SMEM_BYTES>>>(
        p_mg, KRn, (size_t)Tn * KRn, p_qbtg, KRn, (size_t)In * KRn,
        p_gug, In, (size_t)Tn * In, In, KRn, nullptr, nullptr, gate_scale, In, nullptr, p_cnt, nullptr);
    gemm_tn<2><<<GRID(In, Fn), 256, SMEM_BYTES>>>(
        p_mu, KRn, (size_t)Tn * KRn, p_qbtu, KRn, (size_t)In * KRn,
        p_guu, In, (size_t)Tn * In, In, KRn, nullptr, nullptr, up_scale, In, nullptr, p_cnt, nullptr);

    // 7. hmid = silu(gate)*up (compacted)
    {
        size_t cntT = (size_t)Fn * Tn * In;
        fuse_kernel<<<(int)((cntT + 255) / 256), 256>>>(p_gug, p_guu, p_cnt, p_hmid);
    }

    // 8. down LoRA a: md = (hmid @ dqa^T) * soft
    gemm_tn<1><<<GRID(KRn, Fn), 256, SMEM_BYTES>>>(
        p_hmid, In, (size_t)Tn * In, down_qa, In, (size_t)KRn * In,
        p_md, KRn, (size_t)Tn * KRn, KRn, In, p_soft, nullptr, nullptr, 0, nullptr, p_cnt, p_tok);

    // 9. mixd = down_scale[n] * (md @ qbtd^T)
    gemm_tn<3><<<GRID(Hn, Fn), 256, SMEM_BYTES>>>(
        p_md, KRn, (size_t)Tn * KRn, p_qbtd, KRn, (size_t)Hn * KRn,
        p_mixd, Hn, (size_t)Tn * Hn, Hn, KRn, nullptr, nullptr, down_scale, Hn, nullptr, p_cnt, nullptr);

    // 10. down GEMM fused: down = scalar[tok,z]*(hmid @ dW^T + mixd)
    gemm_tn<4><<<GRID(Hn, Fn), 256, SMEM_BYTES>>>(
        p_hmid, In, (size_t)Tn * In, down_W, In, (size_t)Hn * In,
        p_down, Hn, (size_t)Tn * Hn, Hn, In, nullptr, p_scal, nullptr, 0, p_mixd, p_cnt, p_tok);

    // 11. shared path (dense)
    gemm_tn<0><<<GRID(ISHn, 1), 256, SMEM_BYTES>>>(
        x, Hn, 0, sh_gate_W, Hn, 0,
        p_shg, ISHn, 0, ISHn, Hn, nullptr, nullptr, nullptr, 0, nullptr, nullptr, nullptr);
    gemm_tn<0><<<GRID(ISHn, 1), 256, SMEM_BYTES>>>(
        x, Hn, 0, sh_up_W, Hn, 0,
        p_shu, ISHn, 0, ISHn, Hn, nullptr, nullptr, nullptr, 0, nullptr, nullptr, nullptr);
    {
        size_t cntT = (size_t)Tn * ISHn;
        swiglu_kernel<<<(int)((cntT + 255) / 256), 256>>>(p_shg, p_shu, p_shm);
    }
    gemm_tn<0><<<GRID(Hn, 1), 256, SMEM_BYTES>>>(
        p_shm, ISHn, 0, sh_down_W, ISHn, 0,
        out, Hn, 0, Hn, ISHn, nullptr, nullptr, nullptr, 0, nullptr, nullptr, nullptr);

    // 12. out += gathered expert outputs
    reduce_kernel<<<(Tn * Hn + 255) / 256, 256>>>(out, p_down, p_pos);

#undef GRID
    (void)in_sizes; (void)n_in; (void)out_size;
}